// round 15
// baseline (speedup 1.0000x reference)
#include <cuda_runtime.h>
#include <cstdint>

// SPHeroConv fused R7: stage-2 via mma.sync (bf16 hi/lo, 3 passes) — classic
// tensor-core PTX that compiles at compute_103 (no tcgen05).
//  prep kernel: kern [256x64] fp32 -> per-lane u64 B fragments (bf16 hi/lo)
//               in __device__ scratch, mma.m16n8k16 col-layout.
//  main kernel (BM=64 points, 256 thr, 2 CTA/SM):
//   phase A: edge-parallel sph precompute -> smem
//   phase B: gather feat (16 thr/row), fp32 FFMA2 accumulate, split bf16 hi/lo,
//            store A[m=64][k=256] as 8x16bf16 ldmatrix tiles (XOR row swizzle)
//   stage 2: 8 warps x (16x32 tile): ldmatrix.x4 A, LDG.64 B frags,
//            mma.sync m16n8k16: AhBh + AhBl + AlBh, fp32 accum
//   epilogue: + bias, STG.64

#define CDIM 64
#define FDIM 64
#define BM   64
#define NTHR 256
#define EPC  1024

// smem byte offsets
#define A_HI 0
#define A_LO 32768
#define SPH  65536
#define NSO  81920
#define SMEM_BYTES 86016

typedef unsigned long long u64;

__device__ u64 Bp_hi[4096];   // [nt(8)][ks(16)][lane(32)]
__device__ u64 Bp_lo[4096];

__device__ __forceinline__ uint32_t smem_u32(const void* p) {
    uint32_t a;
    asm("{ .reg .u64 t; cvta.to.shared.u64 t, %1; cvt.u32.u64 %0, t; }" : "=r"(a) : "l"(p));
    return a;
}
__device__ __forceinline__ u64 dup2f(float x) {
    u64 r; asm("mov.b64 %0, {%1, %1};" : "=l"(r) : "f"(x)); return r;
}
__device__ __forceinline__ void ffma2(u64& d, u64 a, u64 b) {
    asm("fma.rn.f32x2 %0, %1, %2, %0;" : "+l"(d) : "l"(a), "l"(b));
}
__device__ __forceinline__ float2 unpk2(u64 v) {
    float lo, hi; asm("mov.b64 {%0, %1}, %2;" : "=f"(lo), "=f"(hi) : "l"(v));
    return make_float2(lo, hi);
}
// pack (lo, hi) -> bf16x2, lo in low half
__device__ __forceinline__ uint32_t cvt_bf16x2(float lo, float hi) {
    uint32_t r; asm("cvt.rn.satfinite.bf16x2.f32 %0, %1, %2;" : "=r"(r) : "f"(hi), "f"(lo));
    return r;
}
__device__ __forceinline__ float bf_lo(uint32_t p) { return __uint_as_float(p << 16); }
__device__ __forceinline__ float bf_hi(uint32_t p) { return __uint_as_float(p & 0xffff0000u); }

__device__ __forceinline__ void ldsm_x4(uint32_t& r0, uint32_t& r1, uint32_t& r2, uint32_t& r3,
                                        uint32_t addr) {
    asm volatile("ldmatrix.sync.aligned.m8n8.x4.shared.b16 {%0,%1,%2,%3}, [%4];"
                 : "=r"(r0), "=r"(r1), "=r"(r2), "=r"(r3) : "r"(addr));
}
__device__ __forceinline__ void mma16816(float* c, const uint32_t* a, uint32_t b0, uint32_t b1) {
    asm volatile("mma.sync.aligned.m16n8k16.row.col.f32.bf16.bf16.f32 "
                 "{%0,%1,%2,%3}, {%4,%5,%6,%7}, {%8,%9}, {%0,%1,%2,%3};"
                 : "+f"(c[0]), "+f"(c[1]), "+f"(c[2]), "+f"(c[3])
                 : "r"(a[0]), "r"(a[1]), "r"(a[2]), "r"(a[3]), "r"(b0), "r"(b1));
}

// ---------------- prep: kern -> B fragments (hi/lo) --------------------------
__global__ void prep_kernel(const float* __restrict__ kern) {
    const int e  = blockIdx.x * 256 + threadIdx.x;   // 0..4095
    const int ln = e & 31;
    const int frag = e >> 5;          // 0..127
    const int ks = frag & 15;
    const int nt = frag >> 4;         // 0..7
    const int n  = nt * 8 + (ln >> 2);
    const int k0 = ks * 16 + (ln & 3) * 2;
    const float v00 = kern[(k0 + 0) * FDIM + n];
    const float v01 = kern[(k0 + 1) * FDIM + n];
    const float v10 = kern[(k0 + 8) * FDIM + n];
    const float v11 = kern[(k0 + 9) * FDIM + n];
    const uint32_t h0 = cvt_bf16x2(v00, v01);
    const uint32_t h1 = cvt_bf16x2(v10, v11);
    const uint32_t l0 = cvt_bf16x2(v00 - bf_lo(h0), v01 - bf_hi(h0));
    const uint32_t l1 = cvt_bf16x2(v10 - bf_lo(h1), v11 - bf_hi(h1));
    Bp_hi[e] = ((u64)h1 << 32) | h0;
    Bp_lo[e] = ((u64)l1 << 32) | l0;
}

// A smem tile layout: region(m8, kc) = ((m8*16)+kc)*256 bytes; within region
// 8 rows x 32B (16 bf16, k_in_chunk 0..15), phys row = (m&7) ^ (kc&3).
__global__ __launch_bounds__(NTHR, 2)
void spconv_mma_kernel(const float* __restrict__ feat,      // [N_IN, 64]
                       const float* __restrict__ ipos,      // [N_IN, 3]
                       const float* __restrict__ opos,      // [N_OUT, 3]
                       const float* __restrict__ extents,   // [1]
                       const float* __restrict__ bias,      // [64]
                       const int*   __restrict__ nidx,      // [E]
                       float*       __restrict__ out,       // [N_OUT, 64]
                       int nOut, int deg)
{
    extern __shared__ char smem[];
    const uint32_t sm = smem_u32(smem);
    float4* sphs = (float4*)(smem + SPH);
    int*    ns   = (int*)(smem + NSO);

    const int tid = threadIdx.x;
    const int wid = tid >> 5;
    const int lid = tid & 31;

    // ---------------- phase A: edge-parallel sph precompute ------------------
    {
        const int  epc    = BM * deg;                 // <= 1024
        const long cta_eb = (long)blockIdx.x * epc;
        const float inv_ext = __fdividef(1.0f, extents[0]);
        #pragma unroll
        for (int i = 0; i < 4; i++) {
            const int el = tid + i * NTHR;
            if (el < epc) {
                const int pt = blockIdx.x * BM + el / deg;
                float4 sph = make_float4(0.f, 0.f, 0.f, 0.f);
                int n = 0;
                if (pt < nOut) {
                    n = nidx[cta_eb + el];
                    const float dx = ipos[n * 3 + 0] - opos[pt * 3 + 0];
                    const float dy = ipos[n * 3 + 1] - opos[pt * 3 + 1];
                    const float dz = ipos[n * 3 + 2] - opos[pt * 3 + 2];
                    const float r2p = dx * dx + dy * dy;
                    const float r2  = r2p + dz * dz;
                    const float rinv  = rsqrtf(fmaxf(r2,  1e-20f));
                    const float rpinv = rsqrtf(fmaxf(r2p, 1e-20f));
                    sph.x = (r2 * rinv) * inv_ext;
                    sph.y = dz * rinv;
                    sph.z = dy * rpinv;
                    sph.w = dx * rpinv;
                }
                sphs[el] = sph;
                ns[el]   = n;
            }
        }
    }
    __syncthreads();

    // ---------------- phase B: gather + accumulate + bf16 split -> A ---------
    const int cq   = tid & 15;      // channel quarter-of-quarter: c in [4cq, 4cq+4)
    const int prow = tid >> 4;      // 0..15

    #pragma unroll
    for (int chunk = 0; chunk < 4; chunk++) {
        const int m  = chunk * 16 + prow;
        const int pt = blockIdx.x * BM + m;

        u64 g2[4][2];
        #pragma unroll
        for (int s = 0; s < 4; s++) { g2[s][0] = 0ull; g2[s][1] = 0ull; }

        if (pt < nOut) {
            const int lb = m * deg;
            #pragma unroll 4
            for (int k = 0; k < deg; k++) {
                const int el = lb + k;
                const int n  = ns[el];
                const float4 sph = sphs[el];
                const ulonglong2 w =
                    *reinterpret_cast<const ulonglong2*>(feat + (long)n * CDIM + cq * 4);
                const u64 s0 = dup2f(sph.x), s1 = dup2f(sph.y),
                          s2 = dup2f(sph.z), s3 = dup2f(sph.w);
                ffma2(g2[0][0], s0, w.x); ffma2(g2[0][1], s0, w.y);
                ffma2(g2[1][0], s1, w.x); ffma2(g2[1][1], s1, w.y);
                ffma2(g2[2][0], s2, w.x); ffma2(g2[2][1], s2, w.y);
                ffma2(g2[3][0], s3, w.x); ffma2(g2[3][1], s3, w.y);
            }
        }

        // store: k = s*64 + 4cq + 0..3 -> kc = s*4 + (cq>>2), k_in_chunk = 4*(cq&3)
        const int kcq  = cq >> 2;
        const int bofs = 8 * (cq & 3);
        #pragma unroll
        for (int s = 0; s < 4; s++) {
            const int kc = s * 4 + kcq;
            const uint32_t addr = (uint32_t)((((m >> 3) * 16 + kc) << 8)
                                  + (((m & 7) ^ (kc & 3)) << 5) + bofs);
            const float2 fa = unpk2(g2[s][0]);
            const float2 fb = unpk2(g2[s][1]);
            const uint32_t h2a = cvt_bf16x2(fa.x, fa.y);
            const uint32_t h2b = cvt_bf16x2(fb.x, fb.y);
            asm volatile("st.shared.b64 [%0], %1;"
                         :: "r"(sm + A_HI + addr), "l"(((u64)h2b << 32) | h2a) : "memory");
            const uint32_t l2a = cvt_bf16x2(fa.x - bf_lo(h2a), fa.y - bf_hi(h2a));
            const uint32_t l2b = cvt_bf16x2(fb.x - bf_lo(h2b), fb.y - bf_hi(h2b));
            asm volatile("st.shared.b64 [%0], %1;"
                         :: "r"(sm + A_LO + addr), "l"(((u64)l2b << 32) | l2a) : "memory");
        }
    }

    __syncthreads();

    // ---------------- stage 2: warp-tile 16x32, mma.sync 3 passes ------------
    const int mt  = wid >> 1;       // 0..3 (rows mt*16..+15)
    const int n32 = wid & 1;        // 0..1 (cols n32*32..+31)

    float acc[4][4];
    #pragma unroll
    for (int j = 0; j < 4; j++)
        #pragma unroll
        for (int i = 0; i < 4; i++) acc[j][i] = 0.0f;

    const int m8sel = mt * 2 + ((lid >> 3) & 1);
    const uint32_t half = (uint32_t)((lid >> 4) << 4);
    const int rowid = lid & 7;

    #pragma unroll 4
    for (int ks = 0; ks < 16; ks++) {
        const uint32_t off = (uint32_t)(((m8sel * 16 + ks) << 8)
                              + ((rowid ^ (ks & 3)) << 5)) + half;
        uint32_t ah[4], al[4];
        ldsm_x4(ah[0], ah[1], ah[2], ah[3], sm + A_HI + off);
        ldsm_x4(al[0], al[1], al[2], al[3], sm + A_LO + off);

        #pragma unroll
        for (int j = 0; j < 4; j++) {
            const int f = ((n32 * 4 + j) * 16 + ks) * 32 + lid;
            const u64 bh = Bp_hi[f];
            const u64 bl = Bp_lo[f];
            const uint32_t bh0 = (uint32_t)bh, bh1 = (uint32_t)(bh >> 32);
            const uint32_t bl0 = (uint32_t)bl, bl1 = (uint32_t)(bl >> 32);
            mma16816(acc[j], ah, bh0, bh1);
            mma16816(acc[j], ah, bl0, bl1);
            mma16816(acc[j], al, bh0, bh1);
        }
    }

    // ---------------- epilogue: + bias, store --------------------------------
    {
        const int r0   = mt * 16 + (lid >> 2);
        const int col0 = n32 * 32 + (lid & 3) * 2;
        const int pbase = blockIdx.x * BM;
        #pragma unroll
        for (int j = 0; j < 4; j++) {
            const int cn = col0 + j * 8;
            const float b0 = bias[cn], b1 = bias[cn + 1];
            const int p0 = pbase + r0;
            if (p0 < nOut) {
                float2 v = make_float2(acc[j][0] + b0, acc[j][1] + b1);
                *reinterpret_cast<float2*>(out + (long)p0 * FDIM + cn) = v;
            }
            const int p1 = pbase + r0 + 8;
            if (p1 < nOut) {
                float2 v = make_float2(acc[j][2] + b0, acc[j][3] + b1);
                *reinterpret_cast<float2*>(out + (long)p1 * FDIM + cn) = v;
            }
        }
    }
}

extern "C" void kernel_launch(void* const* d_in, const int* in_sizes, int n_in,
                              void* d_out, int out_size)
{
    const float* feat    = (const float*)d_in[0];
    const float* ipos    = (const float*)d_in[1];
    const float* opos    = (const float*)d_in[2];
    const float* extents = (const float*)d_in[3];
    const float* kern    = (const float*)d_in[4];
    const float* bias    = (const float*)d_in[5];
    const int*   nidx    = (const int*)d_in[6];

    float* out = (float*)d_out;

    const int nOut = in_sizes[2] / 3;
    const int deg  = in_sizes[6] / nOut;

    prep_kernel<<<16, 256>>>(kern);

    cudaFuncSetAttribute(spconv_mma_kernel,
                         cudaFuncAttributeMaxDynamicSharedMemorySize, SMEM_BYTES);
    const int grid = (nOut + BM - 1) / BM;
    spconv_mma_kernel<<<grid, NTHR, SMEM_BYTES>>>(feat, ipos, opos, extents,
                                                  bias, nidx, out, nOut, deg);
}

// round 16
// speedup vs baseline: 1.0210x; 1.0210x over previous
#include <cuda_runtime.h>
#include <cstdint>

// SPHeroConv fused R7: stage-2 via mma.sync (bf16 hi/lo, 3 passes) — classic
// tensor-core PTX that compiles at compute_103 (no tcgen05).
//  prep kernel: kern [256x64] fp32 -> per-lane u64 B fragments (bf16 hi/lo)
//               in __device__ scratch, mma.m16n8k16 col-layout.
//  main kernel (BM=64 points, 256 thr, 2 CTA/SM):
//   phase A: edge-parallel sph precompute -> smem
//   phase B: gather feat (16 thr/row), fp32 FFMA2 accumulate, split bf16 hi/lo,
//            store A[m=64][k=256] as 8x16bf16 ldmatrix tiles (XOR row swizzle)
//   stage 2: 8 warps x (16x32 tile): ldmatrix.x4 A, LDG.64 B frags,
//            mma.sync m16n8k16: AhBh + AhBl + AlBh, fp32 accum
//   epilogue: + bias, STG.64

#define CDIM 64
#define FDIM 64
#define BM   64
#define NTHR 256
#define EPC  1024

// smem byte offsets
#define A_HI 0
#define A_LO 32768
#define SPH  65536
#define NSO  81920
#define SMEM_BYTES 86016

typedef unsigned long long u64;

__device__ u64 Bp_hi[4096];   // [nt(8)][ks(16)][lane(32)]
__device__ u64 Bp_lo[4096];

__device__ __forceinline__ uint32_t smem_u32(const void* p) {
    uint32_t a;
    asm("{ .reg .u64 t; cvta.to.shared.u64 t, %1; cvt.u32.u64 %0, t; }" : "=r"(a) : "l"(p));
    return a;
}
__device__ __forceinline__ u64 dup2f(float x) {
    u64 r; asm("mov.b64 %0, {%1, %1};" : "=l"(r) : "f"(x)); return r;
}
__device__ __forceinline__ void ffma2(u64& d, u64 a, u64 b) {
    asm("fma.rn.f32x2 %0, %1, %2, %0;" : "+l"(d) : "l"(a), "l"(b));
}
__device__ __forceinline__ float2 unpk2(u64 v) {
    float lo, hi; asm("mov.b64 {%0, %1}, %2;" : "=f"(lo), "=f"(hi) : "l"(v));
    return make_float2(lo, hi);
}
// pack (lo, hi) -> bf16x2, lo in low half
__device__ __forceinline__ uint32_t cvt_bf16x2(float lo, float hi) {
    uint32_t r; asm("cvt.rn.satfinite.bf16x2.f32 %0, %1, %2;" : "=r"(r) : "f"(hi), "f"(lo));
    return r;
}
__device__ __forceinline__ float bf_lo(uint32_t p) { return __uint_as_float(p << 16); }
__device__ __forceinline__ float bf_hi(uint32_t p) { return __uint_as_float(p & 0xffff0000u); }

__device__ __forceinline__ void ldsm_x4(uint32_t& r0, uint32_t& r1, uint32_t& r2, uint32_t& r3,
                                        uint32_t addr) {
    asm volatile("ldmatrix.sync.aligned.m8n8.x4.shared.b16 {%0,%1,%2,%3}, [%4];"
                 : "=r"(r0), "=r"(r1), "=r"(r2), "=r"(r3) : "r"(addr));
}
__device__ __forceinline__ void mma16816(float* c, const uint32_t* a, uint32_t b0, uint32_t b1) {
    asm volatile("mma.sync.aligned.m16n8k16.row.col.f32.bf16.bf16.f32 "
                 "{%0,%1,%2,%3}, {%4,%5,%6,%7}, {%8,%9}, {%0,%1,%2,%3};"
                 : "+f"(c[0]), "+f"(c[1]), "+f"(c[2]), "+f"(c[3])
                 : "r"(a[0]), "r"(a[1]), "r"(a[2]), "r"(a[3]), "r"(b0), "r"(b1));
}

// ---------------- prep: kern -> B fragments (hi/lo) --------------------------
__global__ void prep_kernel(const float* __restrict__ kern) {
    const int e  = blockIdx.x * 256 + threadIdx.x;   // 0..4095
    const int ln = e & 31;
    const int frag = e >> 5;          // 0..127
    const int ks = frag & 15;
    const int nt = frag >> 4;         // 0..7
    const int n  = nt * 8 + (ln >> 2);
    const int k0 = ks * 16 + (ln & 3) * 2;
    const float v00 = kern[(k0 + 0) * FDIM + n];
    const float v01 = kern[(k0 + 1) * FDIM + n];
    const float v10 = kern[(k0 + 8) * FDIM + n];
    const float v11 = kern[(k0 + 9) * FDIM + n];
    const uint32_t h0 = cvt_bf16x2(v00, v01);
    const uint32_t h1 = cvt_bf16x2(v10, v11);
    const uint32_t l0 = cvt_bf16x2(v00 - bf_lo(h0), v01 - bf_hi(h0));
    const uint32_t l1 = cvt_bf16x2(v10 - bf_lo(h1), v11 - bf_hi(h1));
    Bp_hi[e] = ((u64)h1 << 32) | h0;
    Bp_lo[e] = ((u64)l1 << 32) | l0;
}

// A smem tile layout: region(m8, kc) = ((m8*16)+kc)*256 bytes; within region
// 8 rows x 32B (16 bf16, k_in_chunk 0..15), phys row = (m&7) ^ (kc&3).
__global__ __launch_bounds__(NTHR, 2)
void spconv_mma_kernel(const float* __restrict__ feat,      // [N_IN, 64]
                       const float* __restrict__ ipos,      // [N_IN, 3]
                       const float* __restrict__ opos,      // [N_OUT, 3]
                       const float* __restrict__ extents,   // [1]
                       const float* __restrict__ bias,      // [64]
                       const int*   __restrict__ nidx,      // [E]
                       float*       __restrict__ out,       // [N_OUT, 64]
                       int nOut, int deg)
{
    extern __shared__ char smem[];
    const uint32_t sm = smem_u32(smem);
    float4* sphs = (float4*)(smem + SPH);
    int*    ns   = (int*)(smem + NSO);

    const int tid = threadIdx.x;
    const int wid = tid >> 5;
    const int lid = tid & 31;

    // ---------------- phase A: edge-parallel sph precompute ------------------
    {
        const int  epc    = BM * deg;                 // <= 1024
        const long cta_eb = (long)blockIdx.x * epc;
        const float inv_ext = __fdividef(1.0f, extents[0]);
        #pragma unroll
        for (int i = 0; i < 4; i++) {
            const int el = tid + i * NTHR;
            if (el < epc) {
                const int pt = blockIdx.x * BM + el / deg;
                float4 sph = make_float4(0.f, 0.f, 0.f, 0.f);
                int n = 0;
                if (pt < nOut) {
                    n = nidx[cta_eb + el];
                    const float dx = ipos[n * 3 + 0] - opos[pt * 3 + 0];
                    const float dy = ipos[n * 3 + 1] - opos[pt * 3 + 1];
                    const float dz = ipos[n * 3 + 2] - opos[pt * 3 + 2];
                    const float r2p = dx * dx + dy * dy;
                    const float r2  = r2p + dz * dz;
                    const float rinv  = rsqrtf(fmaxf(r2,  1e-20f));
                    const float rpinv = rsqrtf(fmaxf(r2p, 1e-20f));
                    sph.x = (r2 * rinv) * inv_ext;
                    sph.y = dz * rinv;
                    sph.z = dy * rpinv;
                    sph.w = dx * rpinv;
                }
                sphs[el] = sph;
                ns[el]   = n;
            }
        }
    }
    __syncthreads();

    // ---------------- phase B: gather + accumulate + bf16 split -> A ---------
    const int cq   = tid & 15;      // channel quarter-of-quarter: c in [4cq, 4cq+4)
    const int prow = tid >> 4;      // 0..15

    #pragma unroll
    for (int chunk = 0; chunk < 4; chunk++) {
        const int m  = chunk * 16 + prow;
        const int pt = blockIdx.x * BM + m;

        u64 g2[4][2];
        #pragma unroll
        for (int s = 0; s < 4; s++) { g2[s][0] = 0ull; g2[s][1] = 0ull; }

        if (pt < nOut) {
            const int lb = m * deg;
            #pragma unroll 4
            for (int k = 0; k < deg; k++) {
                const int el = lb + k;
                const int n  = ns[el];
                const float4 sph = sphs[el];
                const ulonglong2 w =
                    *reinterpret_cast<const ulonglong2*>(feat + (long)n * CDIM + cq * 4);
                const u64 s0 = dup2f(sph.x), s1 = dup2f(sph.y),
                          s2 = dup2f(sph.z), s3 = dup2f(sph.w);
                ffma2(g2[0][0], s0, w.x); ffma2(g2[0][1], s0, w.y);
                ffma2(g2[1][0], s1, w.x); ffma2(g2[1][1], s1, w.y);
                ffma2(g2[2][0], s2, w.x); ffma2(g2[2][1], s2, w.y);
                ffma2(g2[3][0], s3, w.x); ffma2(g2[3][1], s3, w.y);
            }
        }

        // store: k = s*64 + 4cq + 0..3 -> kc = s*4 + (cq>>2), k_in_chunk = 4*(cq&3)
        const int kcq  = cq >> 2;
        const int bofs = 8 * (cq & 3);
        #pragma unroll
        for (int s = 0; s < 4; s++) {
            const int kc = s * 4 + kcq;
            const uint32_t addr = (uint32_t)((((m >> 3) * 16 + kc) << 8)
                                  + (((m & 7) ^ (kc & 3)) << 5) + bofs);
            const float2 fa = unpk2(g2[s][0]);
            const float2 fb = unpk2(g2[s][1]);
            const uint32_t h2a = cvt_bf16x2(fa.x, fa.y);
            const uint32_t h2b = cvt_bf16x2(fb.x, fb.y);
            asm volatile("st.shared.b64 [%0], %1;"
                         :: "r"(sm + A_HI + addr), "l"(((u64)h2b << 32) | h2a) : "memory");
            const uint32_t l2a = cvt_bf16x2(fa.x - bf_lo(h2a), fa.y - bf_hi(h2a));
            const uint32_t l2b = cvt_bf16x2(fb.x - bf_lo(h2b), fb.y - bf_hi(h2b));
            asm volatile("st.shared.b64 [%0], %1;"
                         :: "r"(sm + A_LO + addr), "l"(((u64)l2b << 32) | l2a) : "memory");
        }
    }

    __syncthreads();

    // ---------------- stage 2: warp-tile 16x32, mma.sync 3 passes ------------
    const int mt  = wid >> 1;       // 0..3 (rows mt*16..+15)
    const int n32 = wid & 1;        // 0..1 (cols n32*32..+31)

    float acc[4][4];
    #pragma unroll
    for (int j = 0; j < 4; j++)
        #pragma unroll
        for (int i = 0; i < 4; i++) acc[j][i] = 0.0f;

    const int m8sel = mt * 2 + ((lid >> 3) & 1);
    const uint32_t half = (uint32_t)((lid >> 4) << 4);
    const int rowid = lid & 7;

    #pragma unroll 4
    for (int ks = 0; ks < 16; ks++) {
        const uint32_t off = (uint32_t)(((m8sel * 16 + ks) << 8)
                              + ((rowid ^ (ks & 3)) << 5)) + half;
        uint32_t ah[4], al[4];
        ldsm_x4(ah[0], ah[1], ah[2], ah[3], sm + A_HI + off);
        ldsm_x4(al[0], al[1], al[2], al[3], sm + A_LO + off);

        #pragma unroll
        for (int j = 0; j < 4; j++) {
            const int f = ((n32 * 4 + j) * 16 + ks) * 32 + lid;
            const u64 bh = Bp_hi[f];
            const u64 bl = Bp_lo[f];
            const uint32_t bh0 = (uint32_t)bh, bh1 = (uint32_t)(bh >> 32);
            const uint32_t bl0 = (uint32_t)bl, bl1 = (uint32_t)(bl >> 32);
            mma16816(acc[j], ah, bh0, bh1);
            mma16816(acc[j], ah, bl0, bl1);
            mma16816(acc[j], al, bh0, bh1);
        }
    }

    // ---------------- epilogue: + bias, store --------------------------------
    {
        const int r0   = mt * 16 + (lid >> 2);
        const int col0 = n32 * 32 + (lid & 3) * 2;
        const int pbase = blockIdx.x * BM;
        #pragma unroll
        for (int j = 0; j < 4; j++) {
            const int cn = col0 + j * 8;
            const float b0 = bias[cn], b1 = bias[cn + 1];
            const int p0 = pbase + r0;
            if (p0 < nOut) {
                float2 v = make_float2(acc[j][0] + b0, acc[j][1] + b1);
                *reinterpret_cast<float2*>(out + (long)p0 * FDIM + cn) = v;
            }
            const int p1 = pbase + r0 + 8;
            if (p1 < nOut) {
                float2 v = make_float2(acc[j][2] + b0, acc[j][3] + b1);
                *reinterpret_cast<float2*>(out + (long)p1 * FDIM + cn) = v;
            }
        }
    }
}

extern "C" void kernel_launch(void* const* d_in, const int* in_sizes, int n_in,
                              void* d_out, int out_size)
{
    const float* feat    = (const float*)d_in[0];
    const float* ipos    = (const float*)d_in[1];
    const float* opos    = (const float*)d_in[2];
    const float* extents = (const float*)d_in[3];
    const float* kern    = (const float*)d_in[4];
    const float* bias    = (const float*)d_in[5];
    const int*   nidx    = (const int*)d_in[6];

    float* out = (float*)d_out;

    const int nOut = in_sizes[2] / 3;
    const int deg  = in_sizes[6] / nOut;

    prep_kernel<<<16, 256>>>(kern);

    cudaFuncSetAttribute(spconv_mma_kernel,
                         cudaFuncAttributeMaxDynamicSharedMemorySize, SMEM_BYTES);
    const int grid = (nOut + BM - 1) / BM;
    spconv_mma_kernel<<<grid, NTHR, SMEM_BYTES>>>(feat, ipos, opos, extents,
                                                  bias, nidx, out, nOut, deg);
}